// round 4
// baseline (speedup 1.0000x reference)
#include <cuda_runtime.h>

#define N_FEAT 96
#define MAX_N  50000
#define MAX_E  800000
#define SCAN_T 1024

// Scratch (device globals; no allocation allowed)
__device__ float g_h1[MAX_N * N_FEAT];   // intermediate hop result
__device__ int   g_degi[MAX_N];
__device__ float g_dinv[MAX_N];
__device__ int   g_rowptr[MAX_N + 1];
__device__ int   g_cursor[MAX_N];
__device__ int2  g_csr[MAX_E];           // .x = src, .y = __float_as_int(norm)
__device__ int   g_is64;

// ---------------------------------------------------------------------------
// Detect whether edge_index is int64 or int32.
// Reads only within the first 2*E 32-bit words (valid under either dtype).
// int64 -> odd words are high halves of small indices -> all zero.
// int32 -> odd words are random node indices -> essentially never all zero.
__global__ void k_detect(const unsigned int* __restrict__ ei32, int E) {
    __shared__ unsigned int acc;
    if (threadIdx.x == 0) acc = 0u;
    __syncthreads();
    unsigned int v = 0u;
    int W = 2 * E;
    int stride = W / 1024; if (stride < 1) stride = 1;
    for (int i = threadIdx.x; i < 1024; i += blockDim.x) {
        long long w = ((long long)i * stride) | 1;   // odd word
        if (w < W) v |= ei32[w];
    }
    atomicOr(&acc, v);
    __syncthreads();
    if (threadIdx.x == 0) g_is64 = (acc == 0u) ? 1 : 0;
}

__global__ void k_zero(int N) {
    int i = blockIdx.x * blockDim.x + threadIdx.x;
    if (i < N) g_degi[i] = 0;
}

// In-degree count over dst, reading the raw edge buffer (either dtype).
__global__ void k_deg(const void* __restrict__ ei, int E) {
    int e = blockIdx.x * blockDim.x + threadIdx.x;
    if (e >= E) return;
    int d;
    if (g_is64) d = (int)((const long long*)ei)[e + E];
    else        d = ((const int*)ei)[e + E];
    atomicAdd(&g_degi[d], 1);
}

// Single-block exclusive scan over N=50k: rowptr + cursor init + dinv.
__global__ void k_scan(int N) {
    __shared__ int part[SCAN_T];
    int tid = threadIdx.x;
    int chunk = (N + SCAN_T - 1) / SCAN_T;
    int start = tid * chunk;
    int stop  = min(start + chunk, N);
    int sum = 0;
    for (int i = start; i < stop; i++) sum += g_degi[i];
    part[tid] = sum;
    __syncthreads();
    // inclusive Hillis-Steele scan on partials
    for (int d = 1; d < SCAN_T; d <<= 1) {
        int t = (tid >= d) ? part[tid - d] : 0;
        __syncthreads();
        part[tid] += t;
        __syncthreads();
    }
    int off = part[tid] - sum;     // exclusive prefix for this chunk
    for (int i = start; i < stop; i++) {
        int dg = g_degi[i];
        g_rowptr[i] = off;
        g_cursor[i] = off;
        g_dinv[i]   = rsqrtf((float)(dg + 1));   // +1 for self-loop
        off += dg;
    }
    if (tid == SCAN_T - 1) g_rowptr[N] = off;
}

// Scatter edges into CSR-by-dst, packing (src, norm) per slot.
__global__ void k_scatter(const void* __restrict__ ei, int E) {
    int e = blockIdx.x * blockDim.x + threadIdx.x;
    if (e >= E) return;
    int s, d;
    if (g_is64) {
        const long long* p = (const long long*)ei;
        s = (int)p[e]; d = (int)p[e + E];
    } else {
        const int* p = (const int*)ei;
        s = p[e]; d = p[e + E];
    }
    float nrm = g_dinv[s] * g_dinv[d];
    int pos = atomicAdd(&g_cursor[d], 1);
    g_csr[pos] = make_int2(s, __float_as_int(nrm));
}

// ---------------------------------------------------------------------------
// One warp per dst node: hout[d,:] = dinv[d]^2 * hin[d,:] + sum norm*hin[src,:]
// Register accumulation, no atomics, single coalesced row store.

__device__ __forceinline__ void hop_row(const float* __restrict__ hin,
                                        float* __restrict__ hout,
                                        int node, int lane) {
    int beg = g_rowptr[node];
    int end = g_rowptr[node + 1];
    float di = g_dinv[node];
    float d2 = di * di;
    const float* own = hin + (size_t)node * N_FEAT;
    float a0 = d2 * own[lane];
    float a1 = d2 * own[lane + 32];
    float a2 = d2 * own[lane + 64];
    for (int e = beg; e < end; e++) {
        int2 en = g_csr[e];                 // broadcast load
        const float* pin = hin + (size_t)en.x * N_FEAT;
        float nrm = __int_as_float(en.y);
        a0 += nrm * pin[lane];
        a1 += nrm * pin[lane + 32];
        a2 += nrm * pin[lane + 64];
    }
    float* po = hout + (size_t)node * N_FEAT;
    po[lane]      = a0;
    po[lane + 32] = a1;
    po[lane + 64] = a2;
}

__global__ void k_hop1(const float* __restrict__ x, int N) {
    int w = (blockIdx.x * blockDim.x + threadIdx.x) >> 5;
    if (w >= N) return;
    hop_row(x, g_h1, w, threadIdx.x & 31);
}

__global__ void k_hop2(float* __restrict__ out, int N) {
    int w = (blockIdx.x * blockDim.x + threadIdx.x) >> 5;
    if (w >= N) return;
    hop_row(g_h1, out, w, threadIdx.x & 31);
}

// ---------------------------------------------------------------------------
extern "C" void kernel_launch(void* const* d_in, const int* in_sizes, int n_in,
                              void* d_out, int out_size) {
    const float* x  = (const float*)d_in[0];
    const void*  ei = d_in[1];
    int N = in_sizes[0] / N_FEAT;      // 50000
    int E = in_sizes[1] / 2;           // 800000
    float* out = (float*)d_out;

    const int T = 256;

    k_detect <<<1, 256>>>((const unsigned int*)ei, E);
    k_zero   <<<(N + T - 1) / T, T>>>(N);
    k_deg    <<<(E + T - 1) / T, T>>>(ei, E);
    k_scan   <<<1, SCAN_T>>>(N);
    k_scatter<<<(E + T - 1) / T, T>>>(ei, E);

    int hopBlocks = (N + (T / 32) - 1) / (T / 32);   // one warp per node
    k_hop1<<<hopBlocks, T>>>(x, N);
    k_hop2<<<hopBlocks, T>>>(out, N);
}

// round 5
// speedup vs baseline: 2.1703x; 2.1703x over previous
#include <cuda_runtime.h>

#define N_FEAT 96
#define MAX_N  50000
#define MAX_E  800000
#define SCAN_B 256                      // block size for hierarchical scan
#define MAX_BLOCKS ((MAX_N + SCAN_B - 1) / SCAN_B)   // 196

// Scratch (device globals; no allocation allowed)
__device__ float g_h1[MAX_N * N_FEAT];   // intermediate hop result
__device__ int   g_degi[MAX_N];
__device__ float g_dinv[MAX_N];
__device__ int   g_rowptr[MAX_N + 1];
__device__ int   g_cursor[MAX_N];
__device__ int2  g_csr[MAX_E];           // .x = src, .y = __float_as_int(norm)
__device__ int   g_is64;
__device__ int   g_bsum[MAX_BLOCKS];
__device__ int   g_boff[MAX_BLOCKS];

// ---------------------------------------------------------------------------
// Detect whether edge_index is int64 or int32.
// Reads only within the first 2*E 32-bit words (valid under either dtype).
__global__ void k_detect(const unsigned int* __restrict__ ei32, int E) {
    __shared__ unsigned int acc;
    if (threadIdx.x == 0) acc = 0u;
    __syncthreads();
    unsigned int v = 0u;
    int W = 2 * E;
    int stride = W / 1024; if (stride < 1) stride = 1;
    for (int i = threadIdx.x; i < 1024; i += blockDim.x) {
        long long w = ((long long)i * stride) | 1;   // odd word
        if (w < W) v |= ei32[w];
    }
    atomicOr(&acc, v);
    __syncthreads();
    if (threadIdx.x == 0) g_is64 = (acc == 0u) ? 1 : 0;
}

__global__ void k_zero(int N) {
    int i = blockIdx.x * blockDim.x + threadIdx.x;
    if (i < N) g_degi[i] = 0;
}

// In-degree count over dst, reading the raw edge buffer (either dtype).
__global__ void k_deg(const void* __restrict__ ei, int E) {
    int e = blockIdx.x * blockDim.x + threadIdx.x;
    if (e >= E) return;
    int d;
    if (g_is64) d = (int)((const long long*)ei)[e + E];
    else        d = ((const int*)ei)[e + E];
    atomicAdd(&g_degi[d], 1);
}

// ---- 3-phase hierarchical exclusive scan of g_degi -> g_rowptr ----

// Phase 1: per-block sums
__global__ void k_bsum(int N) {
    __shared__ int sh[SCAN_B];
    int i = blockIdx.x * SCAN_B + threadIdx.x;
    sh[threadIdx.x] = (i < N) ? g_degi[i] : 0;
    __syncthreads();
    for (int s = SCAN_B / 2; s > 0; s >>= 1) {
        if (threadIdx.x < s) sh[threadIdx.x] += sh[threadIdx.x + s];
        __syncthreads();
    }
    if (threadIdx.x == 0) g_bsum[blockIdx.x] = sh[0];
}

// Phase 2: scan the (<=256) block sums in one block
__global__ void k_bscan(int nblocks, int N) {
    __shared__ int sh[SCAN_B];
    int tid = threadIdx.x;
    int v = (tid < nblocks) ? g_bsum[tid] : 0;
    sh[tid] = v;
    __syncthreads();
    for (int d = 1; d < SCAN_B; d <<= 1) {
        int t = (tid >= d) ? sh[tid - d] : 0;
        __syncthreads();
        sh[tid] += t;
        __syncthreads();
    }
    if (tid < nblocks) g_boff[tid] = sh[tid] - v;   // exclusive
    if (tid == SCAN_B - 1) g_rowptr[N] = sh[SCAN_B - 1];  // total edge count
}

// Phase 3: per-block exclusive scan + offset; emit rowptr/cursor/dinv
__global__ void k_apply(int N) {
    __shared__ int sh[SCAN_B];
    int tid = threadIdx.x;
    int i = blockIdx.x * SCAN_B + tid;
    int dg = (i < N) ? g_degi[i] : 0;
    sh[tid] = dg;
    __syncthreads();
    for (int d = 1; d < SCAN_B; d <<= 1) {
        int t = (tid >= d) ? sh[tid - d] : 0;
        __syncthreads();
        sh[tid] += t;
        __syncthreads();
    }
    if (i < N) {
        int off = g_boff[blockIdx.x] + sh[tid] - dg;   // exclusive prefix
        g_rowptr[i] = off;
        g_cursor[i] = off;
        g_dinv[i]   = rsqrtf((float)(dg + 1));         // +1 for self-loop
    }
}

// Scatter edges into CSR-by-dst, packing (src, norm) per slot.
__global__ void k_scatter(const void* __restrict__ ei, int E) {
    int e = blockIdx.x * blockDim.x + threadIdx.x;
    if (e >= E) return;
    int s, d;
    if (g_is64) {
        const long long* p = (const long long*)ei;
        s = (int)p[e]; d = (int)p[e + E];
    } else {
        const int* p = (const int*)ei;
        s = p[e]; d = p[e + E];
    }
    float nrm = g_dinv[s] * g_dinv[d];
    int pos = atomicAdd(&g_cursor[d], 1);
    g_csr[pos] = make_int2(s, __float_as_int(nrm));
}

// ---------------------------------------------------------------------------
// One warp per dst node: hout[d,:] = dinv[d]^2 * hin[d,:] + sum norm*hin[src,:]
// Register accumulation, no atomics, single coalesced row store.

__device__ __forceinline__ void hop_row(const float* __restrict__ hin,
                                        float* __restrict__ hout,
                                        int node, int lane) {
    int beg = g_rowptr[node];
    int end = g_rowptr[node + 1];
    float di = g_dinv[node];
    float d2 = di * di;
    const float* own = hin + (size_t)node * N_FEAT;
    float a0 = d2 * own[lane];
    float a1 = d2 * own[lane + 32];
    float a2 = d2 * own[lane + 64];
    for (int e = beg; e < end; e++) {
        int2 en = g_csr[e];                 // broadcast load
        const float* pin = hin + (size_t)en.x * N_FEAT;
        float nrm = __int_as_float(en.y);
        a0 += nrm * pin[lane];
        a1 += nrm * pin[lane + 32];
        a2 += nrm * pin[lane + 64];
    }
    float* po = hout + (size_t)node * N_FEAT;
    po[lane]      = a0;
    po[lane + 32] = a1;
    po[lane + 64] = a2;
}

__global__ void k_hop1(const float* __restrict__ x, int N) {
    int w = (blockIdx.x * blockDim.x + threadIdx.x) >> 5;
    if (w >= N) return;
    hop_row(x, g_h1, w, threadIdx.x & 31);
}

__global__ void k_hop2(float* __restrict__ out, int N) {
    int w = (blockIdx.x * blockDim.x + threadIdx.x) >> 5;
    if (w >= N) return;
    hop_row(g_h1, out, w, threadIdx.x & 31);
}

// ---------------------------------------------------------------------------
extern "C" void kernel_launch(void* const* d_in, const int* in_sizes, int n_in,
                              void* d_out, int out_size) {
    const float* x  = (const float*)d_in[0];
    const void*  ei = d_in[1];
    int N = in_sizes[0] / N_FEAT;      // 50000
    int E = in_sizes[1] / 2;           // 800000
    float* out = (float*)d_out;

    const int T = 256;
    int nScanBlocks = (N + SCAN_B - 1) / SCAN_B;   // 196

    k_detect <<<1, 256>>>((const unsigned int*)ei, E);
    k_zero   <<<(N + T - 1) / T, T>>>(N);
    k_deg    <<<(E + T - 1) / T, T>>>(ei, E);
    k_bsum   <<<nScanBlocks, SCAN_B>>>(N);
    k_bscan  <<<1, SCAN_B>>>(nScanBlocks, N);
    k_apply  <<<nScanBlocks, SCAN_B>>>(N);
    k_scatter<<<(E + T - 1) / T, T>>>(ei, E);

    int hopBlocks = (N + (T / 32) - 1) / (T / 32);   // one warp per node
    k_hop1<<<hopBlocks, T>>>(x, N);
    k_hop2<<<hopBlocks, T>>>(out, N);
}